// round 16
// baseline (speedup 1.0000x reference)
#include <cuda_runtime.h>
#include <cuda_fp16.h>
#include <cstdint>

#define N_C 16384
#define N_S 16384
#define DD  2688

#define BM 128
#define BN 128
#define BK 64                     // fp16 per K-chunk (128 B rows)
#define KCH (DD / BK)             // 42
#define NSPLIT 2
#define NTB ((N_S / NSPLIT) / BN) // 64 N-tiles per CTA
#define GTOT (NTB * KCH)          // 2688 chunks per CTA

#define STR 144                   // smem row stride: 128B data + 16B pad
#define A_TILE (128 * STR)        // 18432
#define B_TILE (128 * STR)        // 18432
#define STAGE (A_TILE + B_TILE)   // 36864
#define NSTAGE 3
#define SMEM_TOTAL (NSTAGE * STAGE)  // 110592

#define NTHREADS 512              // 16 warps: 4(M) x 4(N), 32x32 tile per warp
#define CAP 768
#define TAU 0.02f

// ---------------- device scratch (symbols only touched in device code) ----------------
__device__ __half g_C_hi[(size_t)N_C * DD];
__device__ __half g_S_hi[(size_t)N_S * DD];
__device__ float g_inv_s[N_S];
__device__ unsigned g_rowmax_u[N_C];      // monotonic-encoded float, atomicMax-merged
__device__ int   g_cnt[N_C];
__device__ unsigned long long g_cand[(size_t)N_C * CAP];

// ---------------- helpers ----------------
__device__ __forceinline__ uint32_t smem_u32(const void* p) {
    uint32_t a;
    asm("{ .reg .u64 t; cvta.to.shared.u64 t, %1; cvt.u32.u64 %0, t; }" : "=r"(a) : "l"(p));
    return a;
}
__device__ __forceinline__ void cp16(uint32_t s, const void* g) {
    asm volatile("cp.async.cg.shared.global [%0], [%1], 16;" :: "r"(s), "l"(g));
}
#define CP_COMMIT() asm volatile("cp.async.commit_group;" ::: "memory")
#define CP_WAIT1()  asm volatile("cp.async.wait_group 1;" ::: "memory")

__device__ __forceinline__ void ldsm_x4(uint32_t* r, uint32_t addr) {
    asm volatile("ldmatrix.sync.aligned.m8n8.x4.shared.b16 {%0,%1,%2,%3}, [%4];"
                 : "=r"(r[0]), "=r"(r[1]), "=r"(r[2]), "=r"(r[3]) : "r"(addr));
}
// fp16-accumulate MMA: D/C are 2 x f16x2 regs (c0c1 | c2c3), same cell mapping as f32 form
__device__ __forceinline__ void mma16816_h(uint32_t* c, const uint32_t* a,
                                           uint32_t b0, uint32_t b1) {
    asm volatile("mma.sync.aligned.m16n8k16.row.col.f16.f16.f16.f16 "
                 "{%0,%1}, {%2,%3,%4,%5}, {%6,%7}, {%0,%1};"
                 : "+r"(c[0]), "+r"(c[1])
                 : "r"(a[0]), "r"(a[1]), "r"(a[2]), "r"(a[3]), "r"(b0), "r"(b1));
}
__device__ __forceinline__ unsigned mono_enc(float v) {
    unsigned u = __float_as_uint(v);
    return (u & 0x80000000u) ? ~u : (u | 0x80000000u);
}
__device__ __forceinline__ float mono_dec(unsigned u) {
    unsigned b = (u & 0x80000000u) ? (u ^ 0x80000000u) : ~u;
    return __uint_as_float(b);
}

// ---------------- small kernels ----------------
__global__ void init_kernel() {
    int i = blockIdx.x * blockDim.x + threadIdx.x;
    if (i < N_C) { g_cnt[i] = 0; g_rowmax_u[i] = 0u; }
}

// fp32 -> fp16; for which==1 (style) also computes inv row norms in the same pass.
__global__ void prep_kernel(const float* __restrict__ X, int which) {
    int row  = blockIdx.x * 8 + (threadIdx.x >> 5);
    int lane = threadIdx.x & 31;
    __half* hi = which ? g_S_hi : g_C_hi;

    const float4* p = (const float4*)(X + (size_t)row * DD);
    ushort4* d4 = (ushort4*)(hi + (size_t)row * DD);
    float sum = 0.f;
    for (int i = lane; i < DD / 4; i += 32) {
        float4 v = p[i];
        sum += v.x * v.x + v.y * v.y + v.z * v.z + v.w * v.w;
        __half h0 = __float2half_rn(v.x);
        __half h1 = __float2half_rn(v.y);
        __half h2 = __float2half_rn(v.z);
        __half h3 = __float2half_rn(v.w);
        ushort4 hp;
        hp.x = *(unsigned short*)&h0; hp.y = *(unsigned short*)&h1;
        hp.z = *(unsigned short*)&h2; hp.w = *(unsigned short*)&h3;
        d4[i] = hp;
    }
    if (which) {
#pragma unroll
        for (int o = 16; o; o >>= 1) sum += __shfl_xor_sync(0xffffffffu, sum, o);
        if (lane == 0) g_inv_s[row] = (float)(1.0 / sqrt((double)sum + 1e-8));
    }
}

// ---------------- phase 1: fp16 GEMM (f16 acc + per-chunk f32 drain) ----------------
// grid (128 M-tiles, 2 N-halves); 512 threads: 16 warps, 4(M) x 4(N), 32x32 per warp.
__global__ __launch_bounds__(NTHREADS, 1) void sim_filter_kernel() {
    extern __shared__ __align__(16) char sbuf[];
    const uint32_t sb = smem_u32(sbuf);

    const int tid = threadIdx.x;
    const int wid = tid >> 5;
    const int lid = tid & 31;
    const int wm  = wid >> 2;          // 0..3 : 32-row M quarter
    const int wn  = wid & 3;           // 0..3 : 32-col N quarter
    const int m_base = blockIdx.x * BM;
    const int s_base = blockIdx.y * (N_S / NSPLIT);

    // ldmatrix lane offsets (within-tile byte offsets)
    const uint32_t a_lane = (uint32_t)(lid & 15) * STR + (uint32_t)(lid >> 4) * 16;
    const uint32_t b_lane = (uint32_t)(((lid >> 4) << 3) + (lid & 7)) * STR
                          + (uint32_t)((lid >> 3) & 1) * 16;

    auto issue_loads = [&](int g) {
        const int kk = g % KCH;
        const int t  = g / KCH;
        const uint32_t st = sb + (g % NSTAGE) * STAGE;
#pragma unroll
        for (int i = 0; i < 2; i++) {           // A: 1024 x 16B
            const int o = i * NTHREADS + tid;
            const int row = o >> 3, seg = o & 7;
            cp16(st + row * STR + seg * 16,
                 g_C_hi + (size_t)(m_base + row) * DD + kk * BK + seg * 8);
        }
#pragma unroll
        for (int i = 0; i < 2; i++) {           // B: 1024 x 16B
            const int o = i * NTHREADS + tid;
            const int row = o >> 3, seg = o & 7;
            cp16(st + A_TILE + row * STR + seg * 16,
                 g_S_hi + (size_t)(s_base + t * BN + row) * DD + kk * BK + seg * 8);
        }
        CP_COMMIT();
    };

    float bestV[4];
#pragma unroll
    for (int i = 0; i < 4; i++) bestV[i] = -3.0e38f;
    const int r_base = m_base + wm * 32 + (lid >> 2);   // rows: +mf*16 (+8)

    float accF[2][4][4];
#pragma unroll
    for (int mf = 0; mf < 2; mf++)
#pragma unroll
        for (int nf = 0; nf < 4; nf++)
#pragma unroll
            for (int q = 0; q < 4; q++) accF[mf][nf][q] = 0.f;

    auto upd = [&](float v, int col, int row, int k) {
        if (v >= bestV[k] - TAU) {
            int idx = atomicAdd(&g_cnt[row], 1);
            if (idx < CAP)
                g_cand[(size_t)row * CAP + idx] =
                    ((unsigned long long)__float_as_uint(v) << 32) | (unsigned)col;
            if (v > bestV[k]) bestV[k] = v;
        }
    };

    issue_loads(0);
    issue_loads(1);

#pragma unroll 1
    for (int g = 0; g < GTOT; ++g) {
        CP_WAIT1();                    // my group g complete
        __syncthreads();               // ALL threads' group g complete + visible
        if (g + 2 < GTOT) issue_loads(g + 2);   // stage (g+2)%3: consumed at g-1
        else CP_COMMIT();

        const uint32_t aS = sb + (g % NSTAGE) * STAGE;
        const uint32_t bS = aS + A_TILE;

        uint32_t accH[2][4][2];        // f16x2 accumulators, drained per chunk
#pragma unroll
        for (int mf = 0; mf < 2; mf++)
#pragma unroll
            for (int nf = 0; nf < 4; nf++) { accH[mf][nf][0] = 0u; accH[mf][nf][1] = 0u; }

#pragma unroll
        for (int ks = 0; ks < 4; ks++) {
            uint32_t b[2][4];
#pragma unroll
            for (int ng = 0; ng < 2; ng++)
                ldsm_x4(b[ng], bS + (wn * 32 + ng * 16) * STR + ks * 32 + b_lane);
            uint32_t a[2][4];
#pragma unroll
            for (int mf = 0; mf < 2; mf++)
                ldsm_x4(a[mf], aS + (wm * 32 + mf * 16) * STR + ks * 32 + a_lane);
#pragma unroll
            for (int mf = 0; mf < 2; mf++)
#pragma unroll
                for (int nf = 0; nf < 4; nf++)
                    mma16816_h(accH[mf][nf], a[mf],
                               b[nf >> 1][(nf & 1) * 2], b[nf >> 1][(nf & 1) * 2 + 1]);
        }

        // drain: f16x2 partial dots (|.| <= ~30, safe) -> fp32 accumulators
#pragma unroll
        for (int mf = 0; mf < 2; mf++)
#pragma unroll
            for (int nf = 0; nf < 4; nf++) {
                float2 lo = __half22float2(*(half2*)&accH[mf][nf][0]);
                float2 hi = __half22float2(*(half2*)&accH[mf][nf][1]);
                accF[mf][nf][0] += lo.x;
                accF[mf][nf][1] += lo.y;
                accF[mf][nf][2] += hi.x;
                accF[mf][nf][3] += hi.y;
            }

        // end of an N-tile: scale, running max + candidate append, reset acc
        if (g % KCH == KCH - 1) {
            const int nt_c = g / KCH;
#pragma unroll
            for (int nf = 0; nf < 4; nf++) {
                const int col0 = s_base + nt_c * BN + wn * 32 + nf * 8 + 2 * (lid & 3);
                const float inv0 = __ldg(&g_inv_s[col0]);
                const float inv1 = __ldg(&g_inv_s[col0 + 1]);
#pragma unroll
                for (int mf = 0; mf < 2; mf++) {
                    const int r0 = r_base + mf * 16;
                    upd(accF[mf][nf][0] * inv0, col0,     r0,     2 * mf);
                    upd(accF[mf][nf][1] * inv1, col0 + 1, r0,     2 * mf);
                    upd(accF[mf][nf][2] * inv0, col0,     r0 + 8, 2 * mf + 1);
                    upd(accF[mf][nf][3] * inv1, col0 + 1, r0 + 8, 2 * mf + 1);
                }
            }
#pragma unroll
            for (int mf = 0; mf < 2; mf++)
#pragma unroll
                for (int nf = 0; nf < 4; nf++)
#pragma unroll
                    for (int q = 0; q < 4; q++) accF[mf][nf][q] = 0.f;
        }
    }

    // ---- merge per-row approx max through smem, atomicMax into g_rowmax_u ----
    __syncthreads();
    float* M = (float*)sbuf;                       // 128 rows x 16 slots
    const int slot = wn * 4 + (lid & 3);
#pragma unroll
    for (int i = 0; i < 4; i++) {
        const int rl = wm * 32 + (i >> 1) * 16 + (lid >> 2) + (i & 1) * 8;
        M[rl * 16 + slot] = bestV[i];
    }
    __syncthreads();
    if (tid < 128) {
        float best = M[tid * 16];
#pragma unroll
        for (int s = 1; s < 16; s++) best = fmaxf(best, M[tid * 16 + s]);
        atomicMax(&g_rowmax_u[m_base + tid], mono_enc(best));
    }
}

// ---------------- phase 2: exact fp32 refine of survivors + gather ----------------
__global__ __launch_bounds__(128) void refine_kernel(const float* __restrict__ C,
                                                     const float* __restrict__ S,
                                                     float* __restrict__ out) {
    const int row = blockIdx.x;
    const int tid = threadIdx.x;
    const int wid = tid >> 5;
    const int lid = tid & 31;

    __shared__ __align__(16) float cs[DD];
    __shared__ int   s_surv[64];
    __shared__ int   s_nsurv;
    __shared__ unsigned long long s_best;

    {
        const float4* src = (const float4*)(C + (size_t)row * DD);
        float4* dst = (float4*)cs;
        for (int i = tid; i < DD / 4; i += 128) dst[i] = src[i];
    }
    if (tid == 0) { s_nsurv = 0; s_best = 0ULL; }
    __syncthreads();

    const int cnt = g_cnt[row];
    bool fallback = (cnt > CAP);

    if (!fallback) {
        const float thr = mono_dec(g_rowmax_u[row]) - TAU;
        for (int i = tid; i < cnt; i += 128) {
            unsigned long long e = g_cand[(size_t)row * CAP + i];
            float v = __uint_as_float((unsigned)(e >> 32));
            if (v >= thr) {
                int k = atomicAdd(&s_nsurv, 1);
                if (k < 64) s_surv[k] = (int)(e & 0xffffffffu);
            }
        }
        __syncthreads();
        if (s_nsurv > 64) fallback = true;
    }
    __syncthreads();

    if (!fallback) {
        const int ns = s_nsurv;
        const float4* cs4 = (const float4*)cs;
        for (int s = wid; s < ns; s += 4) {
            const int col = s_surv[s];
            const float4* sr = (const float4*)(S + (size_t)col * DD);
            float part = 0.f;
            for (int i = lid; i < DD / 4; i += 32) {
                float4 a = cs4[i];
                float4 b = sr[i];
                part += a.x * b.x + a.y * b.y + a.z * b.z + a.w * b.w;
            }
#pragma unroll
            for (int o = 16; o; o >>= 1) part += __shfl_xor_sync(0xffffffffu, part, o);
            if (lid == 0) {
                float v = part * g_inv_s[col];
                unsigned long long key =
                    ((unsigned long long)mono_enc(v) << 32) | (unsigned)(N_S - 1 - col);
                atomicMax(&s_best, key);
            }
        }
    } else {
        unsigned long long lb = 0ULL;
        for (int col = tid; col < N_S; col += 128) {
            const float* sr = S + (size_t)col * DD;
            float dot = 0.f;
            for (int i = 0; i < DD; i++) dot += cs[i] * sr[i];
            float v = dot * g_inv_s[col];
            unsigned long long key =
                ((unsigned long long)mono_enc(v) << 32) | (unsigned)(N_S - 1 - col);
            if (key > lb) lb = key;
        }
        atomicMax(&s_best, lb);
    }
    __syncthreads();

    const int bcol = N_S - 1 - (int)(s_best & 0xffffffffu);
    const float4* src = (const float4*)(S + (size_t)bcol * DD);
    float4* dst = (float4*)(out + (size_t)row * DD);
    for (int i = tid; i < DD / 4; i += 128) dst[i] = src[i];
}

extern "C" void kernel_launch(void* const* d_in, const int* in_sizes, int n_in,
                              void* d_out, int out_size) {
    const float* feats_c = (const float*)d_in[0];
    const float* feats_s = (const float*)d_in[1];
    float* out = (float*)d_out;

    cudaFuncSetAttribute(sim_filter_kernel,
                         cudaFuncAttributeMaxDynamicSharedMemorySize, SMEM_TOTAL);

    init_kernel<<<N_C / 256, 256>>>();
    prep_kernel<<<N_C / 8, 256>>>(feats_c, 0);
    prep_kernel<<<N_S / 8, 256>>>(feats_s, 1);   // split + norms fused

    dim3 grid(N_C / BM, NSPLIT);
    sim_filter_kernel<<<grid, NTHREADS, SMEM_TOTAL>>>();
    refine_kernel<<<N_C, 128>>>(feats_c, feats_s, out);
}

// round 17
// speedup vs baseline: 2.0400x; 2.0400x over previous
#include <cuda_runtime.h>
#include <cuda_fp16.h>
#include <cstdint>

#define N_C 16384
#define N_S 16384
#define DD  2688

#define BM 128
#define BN 128
#define BK 64                     // fp16 per K-chunk (128 B rows)
#define KCH (DD / BK)             // 42
#define NSPLIT 2
#define NTB ((N_S / NSPLIT) / BN) // 64 N-tiles per CTA
#define GTOT (NTB * KCH)          // 2688 chunks per CTA

#define STR 144                   // smem row stride: 128B data + 16B pad
#define A_TILE (128 * STR)        // 18432
#define B_TILE (128 * STR)        // 18432
#define STAGE (A_TILE + B_TILE)   // 36864
#define NSTAGE 3
#define SMEM_TOTAL (NSTAGE * STAGE)  // 110592 -> 2 CTAs/SM

#define NTHREADS 256              // 8 warps: 2(M) x 4(N), 64x32 tile per warp
#define CAP 768
#define TAU 0.008f

// ---------------- device scratch (symbols only touched in device code) ----------------
__device__ __half g_C_hi[(size_t)N_C * DD];
__device__ __half g_S_hi[(size_t)N_S * DD];
__device__ float g_inv_s[N_S];
__device__ unsigned g_rowmax_u[N_C];      // monotonic-encoded float, atomicMax-merged
__device__ int   g_cnt[N_C];
__device__ unsigned long long g_cand[(size_t)N_C * CAP];

// ---------------- helpers ----------------
__device__ __forceinline__ uint32_t smem_u32(const void* p) {
    uint32_t a;
    asm("{ .reg .u64 t; cvta.to.shared.u64 t, %1; cvt.u32.u64 %0, t; }" : "=r"(a) : "l"(p));
    return a;
}
__device__ __forceinline__ void cp16(uint32_t s, const void* g) {
    asm volatile("cp.async.cg.shared.global [%0], [%1], 16;" :: "r"(s), "l"(g));
}
#define CP_COMMIT() asm volatile("cp.async.commit_group;" ::: "memory")
#define CP_WAIT1()  asm volatile("cp.async.wait_group 1;" ::: "memory")

__device__ __forceinline__ void ldsm_x4(uint32_t* r, uint32_t addr) {
    asm volatile("ldmatrix.sync.aligned.m8n8.x4.shared.b16 {%0,%1,%2,%3}, [%4];"
                 : "=r"(r[0]), "=r"(r[1]), "=r"(r[2]), "=r"(r[3]) : "r"(addr));
}
__device__ __forceinline__ void mma16816(float* c, const uint32_t* a,
                                         uint32_t b0, uint32_t b1) {
    asm volatile("mma.sync.aligned.m16n8k16.row.col.f32.f16.f16.f32 "
                 "{%0,%1,%2,%3}, {%4,%5,%6,%7}, {%8,%9}, {%0,%1,%2,%3};"
                 : "+f"(c[0]), "+f"(c[1]), "+f"(c[2]), "+f"(c[3])
                 : "r"(a[0]), "r"(a[1]), "r"(a[2]), "r"(a[3]), "r"(b0), "r"(b1));
}
__device__ __forceinline__ unsigned mono_enc(float v) {
    unsigned u = __float_as_uint(v);
    return (u & 0x80000000u) ? ~u : (u | 0x80000000u);
}
__device__ __forceinline__ float mono_dec(unsigned u) {
    unsigned b = (u & 0x80000000u) ? (u ^ 0x80000000u) : ~u;
    return __uint_as_float(b);
}

// ---------------- small kernels ----------------
__global__ void init_kernel() {
    int i = blockIdx.x * blockDim.x + threadIdx.x;
    if (i < N_C) { g_cnt[i] = 0; g_rowmax_u[i] = 0u; }
}

// fp32 -> fp16; for which==1 (style) also computes inv row norms in the same pass.
__global__ void prep_kernel(const float* __restrict__ X, int which) {
    int row  = blockIdx.x * 8 + (threadIdx.x >> 5);
    int lane = threadIdx.x & 31;
    __half* hi = which ? g_S_hi : g_C_hi;

    const float4* p = (const float4*)(X + (size_t)row * DD);
    ushort4* d4 = (ushort4*)(hi + (size_t)row * DD);
    float sum = 0.f;
    for (int i = lane; i < DD / 4; i += 32) {
        float4 v = p[i];
        sum += v.x * v.x + v.y * v.y + v.z * v.z + v.w * v.w;
        __half h0 = __float2half_rn(v.x);
        __half h1 = __float2half_rn(v.y);
        __half h2 = __float2half_rn(v.z);
        __half h3 = __float2half_rn(v.w);
        ushort4 hp;
        hp.x = *(unsigned short*)&h0; hp.y = *(unsigned short*)&h1;
        hp.z = *(unsigned short*)&h2; hp.w = *(unsigned short*)&h3;
        d4[i] = hp;
    }
    if (which) {
#pragma unroll
        for (int o = 16; o; o >>= 1) sum += __shfl_xor_sync(0xffffffffu, sum, o);
        if (lane == 0) g_inv_s[row] = (float)(1.0 / sqrt((double)sum + 1e-8));
    }
}

// ---------------- phase 1: fp16 GEMM + running max + candidate append ----------------
// grid (128 M-tiles, 2 N-halves); 256 threads: 8 warps, 2(M) x 4(N), 64x32 per warp.
__global__ __launch_bounds__(NTHREADS, 2) void sim_filter_kernel() {
    extern __shared__ __align__(16) char sbuf[];
    const uint32_t sb = smem_u32(sbuf);

    const int tid = threadIdx.x;
    const int wid = tid >> 5;
    const int lid = tid & 31;
    const int wm  = wid >> 2;          // 0..1 : 64-row M half
    const int wn  = wid & 3;           // 0..3 : 32-col N quarter
    const int m_base = blockIdx.x * BM;
    const int s_base = blockIdx.y * (N_S / NSPLIT);

    // ldmatrix lane offsets (within-tile byte offsets)
    const uint32_t a_lane = (uint32_t)(lid & 15) * STR + (uint32_t)(lid >> 4) * 16;
    const uint32_t b_lane = (uint32_t)(((lid >> 4) << 3) + (lid & 7)) * STR
                          + (uint32_t)((lid >> 3) & 1) * 16;

    auto issue_loads = [&](int g) {
        const int kk = g % KCH;
        const int t  = g / KCH;
        const uint32_t st = sb + (g % NSTAGE) * STAGE;
#pragma unroll
        for (int i = 0; i < 4; i++) {           // A: 1024 x 16B
            const int o = i * NTHREADS + tid;
            const int row = o >> 3, seg = o & 7;
            cp16(st + row * STR + seg * 16,
                 g_C_hi + (size_t)(m_base + row) * DD + kk * BK + seg * 8);
        }
#pragma unroll
        for (int i = 0; i < 4; i++) {           // B: 1024 x 16B
            const int o = i * NTHREADS + tid;
            const int row = o >> 3, seg = o & 7;
            cp16(st + A_TILE + row * STR + seg * 16,
                 g_S_hi + (size_t)(s_base + t * BN + row) * DD + kk * BK + seg * 8);
        }
        CP_COMMIT();
    };

    float bestV[8];
#pragma unroll
    for (int i = 0; i < 8; i++) bestV[i] = -3.0e38f;
    const int r_base = m_base + wm * 64 + (lid >> 2);   // rows: +mf*16 (+8)

    float acc[4][4][4];
#pragma unroll
    for (int mf = 0; mf < 4; mf++)
#pragma unroll
        for (int nf = 0; nf < 4; nf++)
#pragma unroll
            for (int q = 0; q < 4; q++) acc[mf][nf][q] = 0.f;

    auto upd = [&](float v, int col, int row, int k) {
        if (v >= bestV[k] - TAU) {
            int idx = atomicAdd(&g_cnt[row], 1);
            if (idx < CAP)
                g_cand[(size_t)row * CAP + idx] =
                    ((unsigned long long)__float_as_uint(v) << 32) | (unsigned)col;
            if (v > bestV[k]) bestV[k] = v;
        }
    };

    issue_loads(0);
    issue_loads(1);

#pragma unroll 1
    for (int g = 0; g < GTOT; ++g) {
        CP_WAIT1();                    // my group g complete
        __syncthreads();               // ALL threads' group g complete + visible
        if (g + 2 < GTOT) issue_loads(g + 2);   // stage (g+2)%3: consumed at g-1
        else CP_COMMIT();

        const uint32_t aS = sb + (g % NSTAGE) * STAGE;
        const uint32_t bS = aS + A_TILE;

#pragma unroll
        for (int ks = 0; ks < 4; ks++) {
            uint32_t b[2][4];
#pragma unroll
            for (int ng = 0; ng < 2; ng++)
                ldsm_x4(b[ng], bS + (wn * 32 + ng * 16) * STR + ks * 32 + b_lane);
            uint32_t a[4][4];
#pragma unroll
            for (int mf = 0; mf < 4; mf++)
                ldsm_x4(a[mf], aS + (wm * 64 + mf * 16) * STR + ks * 32 + a_lane);
#pragma unroll
            for (int mf = 0; mf < 4; mf++)
#pragma unroll
                for (int nf = 0; nf < 4; nf++)
                    mma16816(acc[mf][nf], a[mf],
                             b[nf >> 1][(nf & 1) * 2], b[nf >> 1][(nf & 1) * 2 + 1]);
        }

        // end of an N-tile: scale, running max + candidate append, reset acc
        if (g % KCH == KCH - 1) {
            const int nt_c = g / KCH;
#pragma unroll
            for (int nf = 0; nf < 4; nf++) {
                const int col0 = s_base + nt_c * BN + wn * 32 + nf * 8 + 2 * (lid & 3);
                const float inv0 = __ldg(&g_inv_s[col0]);
                const float inv1 = __ldg(&g_inv_s[col0 + 1]);
#pragma unroll
                for (int mf = 0; mf < 4; mf++) {
                    const int r0 = r_base + mf * 16;
                    upd(acc[mf][nf][0] * inv0, col0,     r0,     2 * mf);
                    upd(acc[mf][nf][1] * inv1, col0 + 1, r0,     2 * mf);
                    upd(acc[mf][nf][2] * inv0, col0,     r0 + 8, 2 * mf + 1);
                    upd(acc[mf][nf][3] * inv1, col0 + 1, r0 + 8, 2 * mf + 1);
                }
            }
#pragma unroll
            for (int mf = 0; mf < 4; mf++)
#pragma unroll
                for (int nf = 0; nf < 4; nf++)
#pragma unroll
                    for (int q = 0; q < 4; q++) acc[mf][nf][q] = 0.f;
        }
    }

    // ---- merge per-row approx max through smem, atomicMax into g_rowmax_u ----
    __syncthreads();
    float* M = (float*)sbuf;                       // 128 rows x 16 slots
    const int slot = wn * 4 + (lid & 3);
#pragma unroll
    for (int i = 0; i < 8; i++) {
        const int rl = wm * 64 + (i >> 1) * 16 + (lid >> 2) + (i & 1) * 8;
        M[rl * 16 + slot] = bestV[i];
    }
    __syncthreads();
    if (tid < 128) {
        float best = M[tid * 16];
#pragma unroll
        for (int s = 1; s < 16; s++) best = fmaxf(best, M[tid * 16 + s]);
        atomicMax(&g_rowmax_u[m_base + tid], mono_enc(best));
    }
}

// ---------------- phase 2: exact fp32 refine of survivors + gather ----------------
__global__ __launch_bounds__(128) void refine_kernel(const float* __restrict__ C,
                                                     const float* __restrict__ S,
                                                     float* __restrict__ out) {
    const int row = blockIdx.x;
    const int tid = threadIdx.x;
    const int wid = tid >> 5;
    const int lid = tid & 31;

    __shared__ __align__(16) float cs[DD];
    __shared__ int   s_surv[64];
    __shared__ int   s_nsurv;
    __shared__ unsigned long long s_best;

    {
        const float4* src = (const float4*)(C + (size_t)row * DD);
        float4* dst = (float4*)cs;
        for (int i = tid; i < DD / 4; i += 128) dst[i] = src[i];
    }
    if (tid == 0) { s_nsurv = 0; s_best = 0ULL; }
    __syncthreads();

    const int cnt = g_cnt[row];
    bool fallback = (cnt > CAP);

    if (!fallback) {
        const float thr = mono_dec(g_rowmax_u[row]) - TAU;
        for (int i = tid; i < cnt; i += 128) {
            unsigned long long e = g_cand[(size_t)row * CAP + i];
            float v = __uint_as_float((unsigned)(e >> 32));
            if (v >= thr) {
                int k = atomicAdd(&s_nsurv, 1);
                if (k < 64) s_surv[k] = (int)(e & 0xffffffffu);
            }
        }
        __syncthreads();
        if (s_nsurv > 64) fallback = true;
    }
    __syncthreads();

    if (!fallback) {
        const int ns = s_nsurv;
        const float4* cs4 = (const float4*)cs;
        // 4 warps process survivors in parallel; float4 dots; shfl reduce
        for (int s = wid; s < ns; s += 4) {
            const int col = s_surv[s];
            const float4* sr = (const float4*)(S + (size_t)col * DD);
            float part = 0.f;
            for (int i = lid; i < DD / 4; i += 32) {
                float4 a = cs4[i];
                float4 b = sr[i];
                part += a.x * b.x + a.y * b.y + a.z * b.z + a.w * b.w;
            }
#pragma unroll
            for (int o = 16; o; o >>= 1) part += __shfl_xor_sync(0xffffffffu, part, o);
            if (lid == 0) {
                float v = part * g_inv_s[col];
                unsigned long long key =
                    ((unsigned long long)mono_enc(v) << 32) | (unsigned)(N_S - 1 - col);
                atomicMax(&s_best, key);
            }
        }
    } else {
        // deterministic full-scan fallback (statistically ~never taken)
        unsigned long long lb = 0ULL;
        for (int col = tid; col < N_S; col += 128) {
            const float* sr = S + (size_t)col * DD;
            float dot = 0.f;
            for (int i = 0; i < DD; i++) dot += cs[i] * sr[i];
            float v = dot * g_inv_s[col];
            unsigned long long key =
                ((unsigned long long)mono_enc(v) << 32) | (unsigned)(N_S - 1 - col);
            if (key > lb) lb = key;
        }
        atomicMax(&s_best, lb);
    }
    __syncthreads();

    const int bcol = N_S - 1 - (int)(s_best & 0xffffffffu);
    const float4* src = (const float4*)(S + (size_t)bcol * DD);
    float4* dst = (float4*)(out + (size_t)row * DD);
    for (int i = tid; i < DD / 4; i += 128) dst[i] = src[i];
}

extern "C" void kernel_launch(void* const* d_in, const int* in_sizes, int n_in,
                              void* d_out, int out_size) {
    const float* feats_c = (const float*)d_in[0];
    const float* feats_s = (const float*)d_in[1];
    float* out = (float*)d_out;

    cudaFuncSetAttribute(sim_filter_kernel,
                         cudaFuncAttributeMaxDynamicSharedMemorySize, SMEM_TOTAL);

    init_kernel<<<N_C / 256, 256>>>();
    prep_kernel<<<N_C / 8, 256>>>(feats_c, 0);
    prep_kernel<<<N_S / 8, 256>>>(feats_s, 1);   // split + norms fused

    dim3 grid(N_C / BM, NSPLIT);
    sim_filter_kernel<<<grid, NTHREADS, SMEM_TOTAL>>>();
    refine_kernel<<<N_C, 128>>>(feats_c, feats_s, out);
}